// round 15
// baseline (speedup 1.0000x reference)
#include <cuda_runtime.h>
#include <math_constants.h>

// ProbAttention: B=4, L=4096, H=8, D=64, FACTOR=5
#define B_ 4
#define L_ 4096
#define H_ 8
#define D_ 64
#define SK_ 45
#define U_  45
#define NSPLIT 64
#define KC 64          // keys per split = L_/NSPLIT
#define PADK 64        // no pad: hot-loop smem reads are row-contiguous

// Scratch (device globals; no allocation allowed)
__device__ float g_M[B_ * H_ * L_];
__device__ int   g_Mtop[B_ * H_ * U_];
__device__ float g_vmean[B_ * H_ * D_];
__device__ float g_pm[B_ * H_ * NSPLIT * U_];
__device__ float g_ps[B_ * H_ * NSPLIT * U_];
__device__ float g_pacc[B_ * H_ * NSPLIT * U_ * D_];   // 23.6 MB

typedef unsigned long long ull;
__device__ __forceinline__ float lo2(ull v) { return __uint_as_float((unsigned)v); }
__device__ __forceinline__ float hi2(ull v) { return __uint_as_float((unsigned)(v >> 32)); }
#define FMA2(acc, a, b) asm("fma.rn.f32x2 %0, %1, %2, %0;" : "+l"(acc) : "l"(a), "l"(b))
#define DUP2(out, x) asm("mov.b64 %0, {%1, %1};" : "=l"(out) : "r"(__float_as_uint(x)))

__device__ __forceinline__ unsigned smem_u32(const void* p) {
    return (unsigned)__cvta_generic_to_shared(p);
}

// ---------------------------------------------------------------------------
// Kernel 1: M scores — monolithic gather kernel, AT the LTS cap (127us).
// Do not fragment this grid (R13) and do not chunk it (R8/R11/R12).
// ---------------------------------------------------------------------------
__global__ void __launch_bounds__(256) kernel_M(const float* __restrict__ Q,
                                                const float* __restrict__ K,
                                                const int* __restrict__ idx) {
    int j = (blockIdx.x * 111) & 16383;      // bijective remap
    int w = j * 8 + (threadIdx.x >> 5);
    int lane = threadIdx.x & 31;
    int li = lane & 7;
    int g  = lane >> 3;
    int l = w & (L_ - 1);
    int h = (w >> 12) & (H_ - 1);
    int b = w >> 15;

    const float4* q4 = (const float4*)(Q + ((b * L_ + l) * H_ + h) * D_);
    float4 qa = q4[li * 2];
    float4 qb = q4[li * 2 + 1];

    const int* ip = idx + l * SK_;
    float mx = -CUDART_INF_F;
    float sm = 0.0f;
#pragma unroll
    for (int sg = 0; sg < 12; sg++) {
        int s = sg * 4 + g;
        bool valid = (s < SK_);
        int kr = ip[valid ? s : 0];
        const float4* k4 = (const float4*)(K + ((b * L_ + kr) * H_ + h) * D_);
        float4 ka = k4[li * 2];
        float4 kb = k4[li * 2 + 1];
        float d = qa.x * ka.x + qa.y * ka.y + qa.z * ka.z + qa.w * ka.w
                + qb.x * kb.x + qb.y * kb.y + qb.z * kb.z + qb.w * kb.w;
        d += __shfl_xor_sync(0xffffffffu, d, 4);
        d += __shfl_xor_sync(0xffffffffu, d, 2);
        d += __shfl_xor_sync(0xffffffffu, d, 1);
        if (valid) { mx = fmaxf(mx, d); sm += d; }
    }
    mx = fmaxf(mx, __shfl_xor_sync(0xffffffffu, mx, 8));
    mx = fmaxf(mx, __shfl_xor_sync(0xffffffffu, mx, 16));
    sm += __shfl_xor_sync(0xffffffffu, sm, 8);
    sm += __shfl_xor_sync(0xffffffffu, sm, 16);
    if (lane == 0) g_M[w] = mx - sm * (1.0f / (float)L_);
}

// ---------------------------------------------------------------------------
// Kernel 2: top-U per (b,h): two-level radix histogram + exact tail select.
// ---------------------------------------------------------------------------
__device__ __forceinline__ unsigned f2key(float f) {
    unsigned u = __float_as_uint(f);
    return (u & 0x80000000u) ? ~u : (u | 0x80000000u);
}

__global__ void __launch_bounds__(256) kernel_topk() {
    __shared__ unsigned skeys[L_];
    __shared__ int hist[256];
    __shared__ unsigned candKey[1024];
    __shared__ int candIdx[1024];
    __shared__ int sT1, sN1, sT2;
    __shared__ int cSel, cCand;
    __shared__ unsigned rk[256];
    __shared__ int ri[256];

    int bh = blockIdx.x;
    int t = threadIdx.x;
    const float* m = g_M + bh * L_;
    for (int i = t; i < L_; i += 256) skeys[i] = f2key(m[i]);
    hist[t] = 0;
    __syncthreads();

    for (int i = t; i < L_; i += 256) atomicAdd(&hist[skeys[i] >> 24], 1);
    __syncthreads();
    if (t == 0) {
        int acc = 0;
        for (int bin = 255; bin >= 0; bin--) {
            if (acc + hist[bin] >= U_) { sT1 = bin; sN1 = acc; break; }
            acc += hist[bin];
        }
    }
    __syncthreads();
    int T1 = sT1, n1 = sN1;
    hist[t] = 0;
    __syncthreads();

    for (int i = t; i < L_; i += 256)
        if ((int)(skeys[i] >> 24) == T1) atomicAdd(&hist[(skeys[i] >> 16) & 255], 1);
    __syncthreads();
    if (t == 0) {
        int acc = n1;
        for (int bin = 255; bin >= 0; bin--) {
            if (acc + hist[bin] >= U_) { sT2 = bin; break; }
            acc += hist[bin];
        }
        cSel = 0; cCand = 0;
    }
    __syncthreads();
    unsigned TH16 = ((unsigned)T1 << 8) | (unsigned)sT2;

    for (int i = t; i < L_; i += 256) {
        unsigned k16 = skeys[i] >> 16;
        if (k16 > TH16) {
            int pos = atomicAdd(&cSel, 1);
            g_Mtop[bh * U_ + pos] = i;
        } else if (k16 == TH16) {
            int pos = atomicAdd(&cCand, 1);
            if (pos < 1024) { candKey[pos] = skeys[i]; candIdx[pos] = i; }
        }
    }
    __syncthreads();
    int ndef = cSel;
    int need = U_ - ndef;
    int nc = (cCand < 1024) ? cCand : 1024;

    for (int it = 0; it < need; it++) {
        unsigned best = 0; int bi = -1;
        for (int jj = t; jj < nc; jj += 256) {
            unsigned v = candKey[jj];
            if (v > best) { best = v; bi = jj; }
        }
        rk[t] = best; ri[t] = bi;
        __syncthreads();
        for (int s = 128; s; s >>= 1) {
            if (t < s && rk[t + s] > rk[t]) { rk[t] = rk[t + s]; ri[t] = ri[t + s]; }
            __syncthreads();
        }
        if (t == 0) {
            g_Mtop[bh * U_ + ndef + it] = candIdx[ri[0]];
            candKey[ri[0]] = 0;
        }
        __syncthreads();
    }
}

// ---------------------------------------------------------------------------
// Kernel 3: V mean (zero + float4 partial sums)
// ---------------------------------------------------------------------------
__global__ void kernel_zero_mean() {
    int i = blockIdx.x * blockDim.x + threadIdx.x;
    if (i < B_ * H_ * D_) g_vmean[i] = 0.0f;
}

__global__ void __launch_bounds__(256) kernel_mean_part(const float* __restrict__ V) {
    int blk = blockIdx.x;              // 1024 blocks
    int seg = blk & 31;
    int bh = blk >> 5;
    int h = bh & (H_ - 1);
    int b = bh >> 3;
    int t = threadIdx.x;
    int d4 = t & 15;
    int sub = t >> 4;
    int l0 = seg * 128;
    const float4* V4 = (const float4*)V;
    float ax = 0.f, ay = 0.f, az = 0.f, aw = 0.f;
#pragma unroll
    for (int i = 0; i < 8; i++) {
        int l = l0 + sub + i * 16;
        float4 v = V4[((size_t)(b * L_ + l) * H_ + h) * 16 + d4];
        ax += v.x; ay += v.y; az += v.z; aw += v.w;
    }
    __shared__ float4 s[16][16];
    s[sub][d4] = make_float4(ax, ay, az, aw);
    __syncthreads();
    if (t < 16) {
        float tx = 0.f, ty = 0.f, tz = 0.f, tw = 0.f;
#pragma unroll
        for (int jj = 0; jj < 16; jj++) {
            float4 v = s[jj][t];
            tx += v.x; ty += v.y; tz += v.z; tw += v.w;
        }
        atomicAdd(&g_vmean[bh * D_ + t * 4 + 0], tx);
        atomicAdd(&g_vmean[bh * D_ + t * 4 + 1], ty);
        atomicAdd(&g_vmean[bh * D_ + t * 4 + 2], tz);
        atomicAdd(&g_vmean[bh * D_ + t * 4 + 3], tw);
    }
}

// ---------------------------------------------------------------------------
// Kernel 4: fill out with V-mean broadcast (float4 stores)
// ---------------------------------------------------------------------------
__global__ void kernel_fill(float* __restrict__ out) {
    unsigned i = blockIdx.x * blockDim.x + threadIdx.x;  // float4 index
    int d4 = i & 15;
    int h = (i >> 4) & 7;
    int b = i >> 19;
    const float4* vm4 = (const float4*)g_vmean;
    float4 v = vm4[(b * H_ + h) * 16 + d4];
    const float inv = 1.0f / (float)L_;
    ((float4*)out)[i] = make_float4(v.x * inv, v.y * inv, v.z * inv, v.w * inv);
}

// ---------------------------------------------------------------------------
// Kernel 5: split-KV attention. PADK=64 (no pad) -> smem 45.3 KB ->
// 5 blocks/SM (40 resident warps, was 32). Hot loops unchanged: all smem
// reads are row-contiguous (conflict-free at stride 64) or broadcast; only
// the one-time K-transpose fill gains a small conflict.
// ---------------------------------------------------------------------------
#define OFF_V   (64 * PADK)                 // 4096 floats
#define OFF_QE  (OFF_V + 64 * PADK)         // 8192
#define OFF_MT  (OFF_QE + 48 * 64)          // 11264
#define SMEM_FLOATS (OFF_MT + 64)
#define SMEM_BYTES  (SMEM_FLOATS * 4)       // 45312 B

__global__ void __launch_bounds__(256) kernel_attn_part(
        const float* __restrict__ Q,
        const float* __restrict__ K,
        const float* __restrict__ V) {
    extern __shared__ float smem[];
    float* sKT = smem;                  // [64][64]  K transposed [d][k]
    float* sV  = smem + OFF_V;          // [64][64]  V natural   [k][d]
    float* sQE = smem + OFF_QE;         // [48][64]  Q rows, then E rows
    int*   sMt = (int*)(smem + OFF_MT);

    int bh = blockIdx.x >> 6;
    int sp = blockIdx.x & 63;
    int h = bh & 7, b = bh >> 3;
    int k0 = sp * KC;
    int t = threadIdx.x;

    {
        const char* vbase = (const char*)(V + ((size_t)(b * L_ + k0) * H_ + h) * D_);
#pragma unroll
        for (int i = 0; i < 4; i++) {
            int e = t + i * 256;
            int row = e >> 4, c = e & 15;
            unsigned dst = smem_u32(sV + row * PADK + c * 4);
            const char* src = vbase + (size_t)row * (H_ * D_ * 4) + c * 16;
            asm volatile("cp.async.cg.shared.global [%0], [%1], 16;"
                         :: "r"(dst), "l"(src));
        }
        asm volatile("cp.async.commit_group;");
    }

    if (t < U_) sMt[t] = g_Mtop[bh * U_ + t];
    __syncthreads();

#pragma unroll
    for (int i = 0; i < 3; i++) {
        int e = t + i * 256;
        int u = e >> 4, c = e & 15;
        float4 q = make_float4(0.f, 0.f, 0.f, 0.f);
        if (u < U_)
            q = *(const float4*)(Q + ((b * L_ + sMt[u]) * H_ + h) * D_ + c * 4);
        *(float4*)(sQE + u * 64 + c * 4) = q;
    }
#pragma unroll
    for (int i = 0; i < 16; i++) {
        int e = t + i * 256;
        int k = e >> 6, d = e & 63;
        sKT[d * PADK + k] = K[((b * L_ + k0 + k) * H_ + h) * D_ + d];
    }
    __syncthreads();

    int kt = t & 15, ut = t >> 4;
    int kk = kt * 4, u0 = ut * 3;

    ull a00 = 0, a01 = 0, a10 = 0, a11 = 0, a20 = 0, a21 = 0;
    {
        const float* q0p = sQE + (u0 + 0) * 64;
        const float* q1p = sQE + (u0 + 1) * 64;
        const float* q2p = sQE + (u0 + 2) * 64;
#pragma unroll 4
        for (int d = 0; d < 64; d += 4) {
            float4 f0 = *(const float4*)(q0p + d);
            float4 f1 = *(const float4*)(q1p + d);
            float4 f2 = *(const float4*)(q2p + d);
#pragma unroll
            for (int j = 0; j < 4; j++) {
                ulonglong2 kv = *(const ulonglong2*)&sKT[(d + j) * PADK + kk];
                float w0 = (j == 0) ? f0.x : (j == 1) ? f0.y : (j == 2) ? f0.z : f0.w;
                float w1 = (j == 0) ? f1.x : (j == 1) ? f1.y : (j == 2) ? f1.z : f1.w;
                float w2 = (j == 0) ? f2.x : (j == 1) ? f2.y : (j == 2) ? f2.z : f2.w;
                ull q0, q1, q2;
                DUP2(q0, w0); DUP2(q1, w1); DUP2(q2, w2);
                FMA2(a00, q0, kv.x); FMA2(a01, q0, kv.y);
                FMA2(a10, q1, kv.x); FMA2(a11, q1, kv.y);
                FMA2(a20, q2, kv.x); FMA2(a21, q2, kv.y);
            }
        }
    }

    float ev[3][4];
    {
        const float sc = 0.125f;
        ull ra[3][2] = {{a00, a01}, {a10, a11}, {a20, a21}};
#pragma unroll
        for (int jj = 0; jj < 3; jj++) {
            float s0 = lo2(ra[jj][0]) * sc, s1 = hi2(ra[jj][0]) * sc;
            float s2 = lo2(ra[jj][1]) * sc, s3 = hi2(ra[jj][1]) * sc;
            float mm = fmaxf(fmaxf(s0, s1), fmaxf(s2, s3));
            mm = fmaxf(mm, __shfl_xor_sync(0xffffffffu, mm, 1));
            mm = fmaxf(mm, __shfl_xor_sync(0xffffffffu, mm, 2));
            mm = fmaxf(mm, __shfl_xor_sync(0xffffffffu, mm, 4));
            mm = fmaxf(mm, __shfl_xor_sync(0xffffffffu, mm, 8));
            float e0 = __expf(s0 - mm), e1 = __expf(s1 - mm);
            float e2 = __expf(s2 - mm), e3 = __expf(s3 - mm);
            float ss = (e0 + e1) + (e2 + e3);
            ss += __shfl_xor_sync(0xffffffffu, ss, 1);
            ss += __shfl_xor_sync(0xffffffffu, ss, 2);
            ss += __shfl_xor_sync(0xffffffffu, ss, 4);
            ss += __shfl_xor_sync(0xffffffffu, ss, 8);
            ev[jj][0] = e0; ev[jj][1] = e1; ev[jj][2] = e2; ev[jj][3] = e3;
            int u = u0 + jj;
            if (kt == 0 && u < U_) {
                g_pm[(bh * NSPLIT + sp) * U_ + u] = mm;
                g_ps[(bh * NSPLIT + sp) * U_ + u] = ss;
            }
        }
    }
    __syncthreads();

#pragma unroll
    for (int jj = 0; jj < 3; jj++)
        *(float4*)(sQE + (u0 + jj) * 64 + kk) =
            make_float4(ev[jj][0], ev[jj][1], ev[jj][2], ev[jj][3]);

    asm volatile("cp.async.wait_group 0;");
    __syncthreads();

    {
        int dd = kk;
        ull c00 = 0, c01 = 0, c10 = 0, c11 = 0, c20 = 0, c21 = 0;
        const float* e0p = sQE + (u0 + 0) * 64;
        const float* e1p = sQE + (u0 + 1) * 64;
        const float* e2p = sQE + (u0 + 2) * 64;
#pragma unroll 4
        for (int k = 0; k < 64; k += 4) {
            float4 f0 = *(const float4*)(e0p + k);
            float4 f1 = *(const float4*)(e1p + k);
            float4 f2 = *(const float4*)(e2p + k);
#pragma unroll
            for (int j = 0; j < 4; j++) {
                ulonglong2 vv = *(const ulonglong2*)&sV[(k + j) * PADK + dd];
                float w0 = (j == 0) ? f0.x : (j == 1) ? f0.y : (j == 2) ? f0.z : f0.w;
                float w1 = (j == 0) ? f1.x : (j == 1) ? f1.y : (j == 2) ? f1.z : f1.w;
                float w2 = (j == 0) ? f2.x : (j == 1) ? f2.y : (j == 2) ? f2.z : f2.w;
                ull e0, e1, e2;
                DUP2(e0, w0); DUP2(e1, w1); DUP2(e2, w2);
                FMA2(c00, e0, vv.x); FMA2(c01, e0, vv.y);
                FMA2(c10, e1, vv.x); FMA2(c11, e1, vv.y);
                FMA2(c20, e2, vv.x); FMA2(c21, e2, vv.y);
            }
        }
        float* pa = g_pacc + (size_t)(bh * NSPLIT + sp) * U_ * D_;
        if (u0 + 0 < U_)
            *(float4*)&pa[(u0 + 0) * D_ + dd] =
                make_float4(lo2(c00), hi2(c00), lo2(c01), hi2(c01));
        if (u0 + 1 < U_)
            *(float4*)&pa[(u0 + 1) * D_ + dd] =
                make_float4(lo2(c10), hi2(c10), lo2(c11), hi2(c11));
        if (u0 + 2 < U_)
            *(float4*)&pa[(u0 + 2) * D_ + dd] =
                make_float4(lo2(c20), hi2(c20), lo2(c21), hi2(c21));
    }
}

// ---------------------------------------------------------------------------
// Kernel 6: combine partials. grid = (U_, B*H), 64 threads.
// ---------------------------------------------------------------------------
__global__ void __launch_bounds__(64) kernel_combine(float* __restrict__ out) {
    __shared__ float sw[NSPLIT];
    __shared__ float red[64];
    int u = blockIdx.x;
    int bh = blockIdx.y;
    int h = bh & 7, b = bh >> 3;
    int t = threadIdx.x;

    float m = g_pm[(bh * NSPLIT + t) * U_ + u];
    float s = g_ps[(bh * NSPLIT + t) * U_ + u];
    red[t] = m;
    __syncthreads();
    for (int st = 32; st; st >>= 1) {
        if (t < st) red[t] = fmaxf(red[t], red[t + st]);
        __syncthreads();
    }
    float M = red[0];
    __syncthreads();
    float e = __expf(m - M);
    red[t] = e * s;
    __syncthreads();
    for (int st = 32; st; st >>= 1) {
        if (t < st) red[t] += red[t + st];
        __syncthreads();
    }
    float inv = 1.0f / red[0];
    sw[t] = e * inv;
    __syncthreads();

    float acc = 0.0f;
    const float* pa = g_pacc + (size_t)bh * NSPLIT * U_ * D_ + u * D_ + t;
#pragma unroll 8
    for (int sp = 0; sp < NSPLIT; sp++)
        acc += pa[(size_t)sp * U_ * D_] * sw[sp];
    int lsel = g_Mtop[bh * U_ + u];
    out[((b * L_ + lsel) * H_ + h) * D_ + t] = acc;
}

// ---------------------------------------------------------------------------
// Launch (R10 structure): main = M, topk, attn, combine;
// side s2 = zero, mean, fill overlapped under M; join before combine.
// ---------------------------------------------------------------------------
extern "C" void kernel_launch(void* const* d_in, const int* in_sizes, int n_in,
                              void* d_out, int out_size) {
    const float* Q = (const float*)d_in[0];
    const float* K = (const float*)d_in[1];
    const float* V = (const float*)d_in[2];
    const int* idx = (const int*)d_in[3];   // int32 (JAX x64 disabled)
    float* out = (float*)d_out;

    static cudaStream_t s2 = nullptr;
    static cudaEvent_t evFork = nullptr, evJoin = nullptr;
    if (s2 == nullptr) {
        cudaStreamCreateWithFlags(&s2, cudaStreamNonBlocking);
        cudaEventCreateWithFlags(&evFork, cudaEventDisableTiming);
        cudaEventCreateWithFlags(&evJoin, cudaEventDisableTiming);
        cudaFuncSetAttribute((const void*)kernel_M,
                             cudaFuncAttributePreferredSharedMemoryCarveout, 0);
        cudaFuncSetAttribute((const void*)kernel_attn_part,
                             cudaFuncAttributeMaxDynamicSharedMemorySize, SMEM_BYTES);
    }

    // Fork side stream off the (possibly capturing) legacy stream.
    cudaEventRecord(evFork, 0);
    cudaStreamWaitEvent(s2, evFork, 0);

    // Main chain (submissions 1,2; slot-4 ncu capture lands on attn below)
    kernel_M<<<(B_ * H_ * L_) / 8, 256>>>(Q, K, idx);
    kernel_topk<<<B_ * H_, 256>>>();

    // Side chain on s2 (runs concurrently with kernel_M)
    kernel_zero_mean<<<(B_ * H_ * D_ + 255) / 256, 256, 0, s2>>>();

    // submission 4: attn (main chain)
    kernel_attn_part<<<B_ * H_ * NSPLIT, 256, SMEM_BYTES>>>(Q, K, V);

    kernel_mean_part<<<B_ * H_ * 32, 256, 0, s2>>>(V);
    kernel_fill<<<(B_ * L_ * H_ * D_ / 4 + 255) / 256, 256, 0, s2>>>(out);

    // Join side stream back, then combine (needs pacc + fill-complete).
    cudaEventRecord(evJoin, s2);
    cudaStreamWaitEvent(0, evJoin, 0);
    kernel_combine<<<dim3(U_, B_ * H_), 64>>>(out);
}

// round 16
// speedup vs baseline: 1.0155x; 1.0155x over previous
#include <cuda_runtime.h>
#include <math_constants.h>

// ProbAttention: B=4, L=4096, H=8, D=64, FACTOR=5
#define B_ 4
#define L_ 4096
#define H_ 8
#define D_ 64
#define SK_ 45
#define U_  45
#define NSPLIT 64
#define KC 64          // keys per split = L_/NSPLIT
#define PADK 68        // pad IS load-bearing (R15: removing it cost 24us)

// Scratch (device globals; no allocation allowed)
__device__ float g_M[B_ * H_ * L_];
__device__ int   g_Mtop[B_ * H_ * U_];
__device__ float g_vmean[B_ * H_ * D_];
__device__ float g_pm[B_ * H_ * NSPLIT * U_];
__device__ float g_ps[B_ * H_ * NSPLIT * U_];
__device__ float g_pacc[B_ * H_ * NSPLIT * U_ * D_];   // 23.6 MB
__device__ int   g_cnt[B_ * H_];        // zero-init; reset by combine each run

typedef unsigned long long ull;
__device__ __forceinline__ float lo2(ull v) { return __uint_as_float((unsigned)v); }
__device__ __forceinline__ float hi2(ull v) { return __uint_as_float((unsigned)(v >> 32)); }
#define FMA2(acc, a, b) asm("fma.rn.f32x2 %0, %1, %2, %0;" : "+l"(acc) : "l"(a), "l"(b))
#define DUP2(out, x) asm("mov.b64 %0, {%1, %1};" : "=l"(out) : "r"(__float_as_uint(x)))

__device__ __forceinline__ unsigned smem_u32(const void* p) {
    return (unsigned)__cvta_generic_to_shared(p);
}

__device__ __forceinline__ unsigned f2key(float f) {
    unsigned u = __float_as_uint(f);
    return (u & 0x80000000u) ? ~u : (u | 0x80000000u);
}

// ---------------------------------------------------------------------------
// Kernel 1: M scores (gather, at the LTS cap) + FUSED per-bh top-45:
// the last block to finish a bh runs that bh's radix top-k inline,
// overlapping selection with the M tail.
// ---------------------------------------------------------------------------
__global__ void __launch_bounds__(256, 4) kernel_M(const float* __restrict__ Q,
                                                   const float* __restrict__ K,
                                                   const int* __restrict__ idx) {
    int j = (blockIdx.x * 111) & 16383;      // bijective remap
    int w0 = j * 8;                          // block's first w (one bh per block)
    int w = w0 + (threadIdx.x >> 5);
    int lane = threadIdx.x & 31;
    int li = lane & 7;
    int g  = lane >> 3;
    int l = w & (L_ - 1);
    int h = (w >> 12) & (H_ - 1);
    int b = w >> 15;
    int bh = w0 >> 12;                       // block's bh

    {
        const float4* q4 = (const float4*)(Q + ((b * L_ + l) * H_ + h) * D_);
        float4 qa = q4[li * 2];
        float4 qb = q4[li * 2 + 1];

        const int* ip = idx + l * SK_;
        float mx = -CUDART_INF_F;
        float sm = 0.0f;
#pragma unroll
        for (int sg = 0; sg < 12; sg++) {
            int s = sg * 4 + g;
            bool valid = (s < SK_);
            int kr = ip[valid ? s : 0];
            const float4* k4 = (const float4*)(K + ((b * L_ + kr) * H_ + h) * D_);
            float4 ka = k4[li * 2];
            float4 kb = k4[li * 2 + 1];
            float d = qa.x * ka.x + qa.y * ka.y + qa.z * ka.z + qa.w * ka.w
                    + qb.x * kb.x + qb.y * kb.y + qb.z * kb.z + qb.w * kb.w;
            d += __shfl_xor_sync(0xffffffffu, d, 4);
            d += __shfl_xor_sync(0xffffffffu, d, 2);
            d += __shfl_xor_sync(0xffffffffu, d, 1);
            if (valid) { mx = fmaxf(mx, d); sm += d; }
        }
        mx = fmaxf(mx, __shfl_xor_sync(0xffffffffu, mx, 8));
        mx = fmaxf(mx, __shfl_xor_sync(0xffffffffu, mx, 16));
        sm += __shfl_xor_sync(0xffffffffu, sm, 8);
        sm += __shfl_xor_sync(0xffffffffu, sm, 16);
        if (lane == 0) g_M[w] = mx - sm * (1.0f / (float)L_);
    }

    // ---- fused top-45: last block of this bh does the selection ----
    __shared__ int sLast;
    __threadfence();
    __syncthreads();
    if (threadIdx.x == 0) {
        int prev = atomicAdd(&g_cnt[bh], 1);
        sLast = (prev == (L_ / 8) - 1);
    }
    __syncthreads();
    if (!sLast) return;

    __shared__ unsigned skeys[L_];
    __shared__ int hist[256];
    __shared__ unsigned candKey[1024];
    __shared__ int candIdx[1024];
    __shared__ int sT1, sN1, sT2;
    __shared__ int cSel, cCand;
    __shared__ unsigned rk[256];
    __shared__ int ri[256];

    int t = threadIdx.x;
    const float* m = g_M + bh * L_;
    for (int i = t; i < L_; i += 256) skeys[i] = f2key(m[i]);
    hist[t] = 0;
    __syncthreads();

    for (int i = t; i < L_; i += 256) atomicAdd(&hist[skeys[i] >> 24], 1);
    __syncthreads();
    if (t == 0) {
        int acc = 0;
        for (int bin = 255; bin >= 0; bin--) {
            if (acc + hist[bin] >= U_) { sT1 = bin; sN1 = acc; break; }
            acc += hist[bin];
        }
    }
    __syncthreads();
    int T1 = sT1, n1 = sN1;
    hist[t] = 0;
    __syncthreads();

    for (int i = t; i < L_; i += 256)
        if ((int)(skeys[i] >> 24) == T1) atomicAdd(&hist[(skeys[i] >> 16) & 255], 1);
    __syncthreads();
    if (t == 0) {
        int acc = n1;
        for (int bin = 255; bin >= 0; bin--) {
            if (acc + hist[bin] >= U_) { sT2 = bin; break; }
            acc += hist[bin];
        }
        cSel = 0; cCand = 0;
    }
    __syncthreads();
    unsigned TH16 = ((unsigned)T1 << 8) | (unsigned)sT2;

    for (int i = t; i < L_; i += 256) {
        unsigned k16 = skeys[i] >> 16;
        if (k16 > TH16) {
            int pos = atomicAdd(&cSel, 1);
            g_Mtop[bh * U_ + pos] = i;
        } else if (k16 == TH16) {
            int pos = atomicAdd(&cCand, 1);
            if (pos < 1024) { candKey[pos] = skeys[i]; candIdx[pos] = i; }
        }
    }
    __syncthreads();
    int ndef = cSel;
    int need = U_ - ndef;
    int nc = (cCand < 1024) ? cCand : 1024;

    for (int it = 0; it < need; it++) {
        unsigned best = 0; int bi = -1;
        for (int jj = t; jj < nc; jj += 256) {
            unsigned v = candKey[jj];
            if (v > best) { best = v; bi = jj; }
        }
        rk[t] = best; ri[t] = bi;
        __syncthreads();
        for (int s = 128; s; s >>= 1) {
            if (t < s && rk[t + s] > rk[t]) { rk[t] = rk[t + s]; ri[t] = ri[t + s]; }
            __syncthreads();
        }
        if (t == 0) {
            g_Mtop[bh * U_ + ndef + it] = candIdx[ri[0]];
            candKey[ri[0]] = 0;
        }
        __syncthreads();
    }
}

// ---------------------------------------------------------------------------
// Kernel 3: V mean (zero + float4 partial sums)
// ---------------------------------------------------------------------------
__global__ void kernel_zero_mean() {
    int i = blockIdx.x * blockDim.x + threadIdx.x;
    if (i < B_ * H_ * D_) g_vmean[i] = 0.0f;
}

__global__ void __launch_bounds__(256) kernel_mean_part(const float* __restrict__ V) {
    int blk = blockIdx.x;              // 1024 blocks
    int seg = blk & 31;
    int bh = blk >> 5;
    int h = bh & (H_ - 1);
    int b = bh >> 3;
    int t = threadIdx.x;
    int d4 = t & 15;
    int sub = t >> 4;
    int l0 = seg * 128;
    const float4* V4 = (const float4*)V;
    float ax = 0.f, ay = 0.f, az = 0.f, aw = 0.f;
#pragma unroll
    for (int i = 0; i < 8; i++) {
        int l = l0 + sub + i * 16;
        float4 v = V4[((size_t)(b * L_ + l) * H_ + h) * 16 + d4];
        ax += v.x; ay += v.y; az += v.z; aw += v.w;
    }
    __shared__ float4 s[16][16];
    s[sub][d4] = make_float4(ax, ay, az, aw);
    __syncthreads();
    if (t < 16) {
        float tx = 0.f, ty = 0.f, tz = 0.f, tw = 0.f;
#pragma unroll
        for (int jj = 0; jj < 16; jj++) {
            float4 v = s[jj][t];
            tx += v.x; ty += v.y; tz += v.z; tw += v.w;
        }
        atomicAdd(&g_vmean[bh * D_ + t * 4 + 0], tx);
        atomicAdd(&g_vmean[bh * D_ + t * 4 + 1], ty);
        atomicAdd(&g_vmean[bh * D_ + t * 4 + 2], tz);
        atomicAdd(&g_vmean[bh * D_ + t * 4 + 3], tw);
    }
}

// ---------------------------------------------------------------------------
// Kernel 4: fill out with V-mean broadcast (float4 stores)
// ---------------------------------------------------------------------------
__global__ void kernel_fill(float* __restrict__ out) {
    unsigned i = blockIdx.x * blockDim.x + threadIdx.x;  // float4 index
    int d4 = i & 15;
    int h = (i >> 4) & 7;
    int b = i >> 19;
    const float4* vm4 = (const float4*)g_vmean;
    float4 v = vm4[(b * H_ + h) * 16 + d4];
    const float inv = 1.0f / (float)L_;
    ((float4*)out)[i] = make_float4(v.x * inv, v.y * inv, v.z * inv, v.w * inv);
}

// ---------------------------------------------------------------------------
// Kernel 5: split-KV attention — exact R14 version (measured 56.7us):
// PADK=68, float4 q/e loads, cp.async V prefetch, register softmax.
// ---------------------------------------------------------------------------
#define OFF_V   (64 * PADK)
#define OFF_QE  (OFF_V + 64 * PADK)
#define OFF_MT  (OFF_QE + 48 * 64)
#define SMEM_FLOATS (OFF_MT + 64)
#define SMEM_BYTES  (SMEM_FLOATS * 4)

__global__ void __launch_bounds__(256) kernel_attn_part(
        const float* __restrict__ Q,
        const float* __restrict__ K,
        const float* __restrict__ V) {
    extern __shared__ float smem[];
    float* sKT = smem;                  // [64][PADK]  K transposed [d][k]
    float* sV  = smem + OFF_V;          // [64][PADK]  V natural   [k][d]
    float* sQE = smem + OFF_QE;         // [48][64]    Q rows, then E rows
    int*   sMt = (int*)(smem + OFF_MT);

    int bh = blockIdx.x >> 6;
    int sp = blockIdx.x & 63;
    int h = bh & 7, b = bh >> 3;
    int k0 = sp * KC;
    int t = threadIdx.x;

    {
        const char* vbase = (const char*)(V + ((size_t)(b * L_ + k0) * H_ + h) * D_);
#pragma unroll
        for (int i = 0; i < 4; i++) {
            int e = t + i * 256;
            int row = e >> 4, c = e & 15;
            unsigned dst = smem_u32(sV + row * PADK + c * 4);
            const char* src = vbase + (size_t)row * (H_ * D_ * 4) + c * 16;
            asm volatile("cp.async.cg.shared.global [%0], [%1], 16;"
                         :: "r"(dst), "l"(src));
        }
        asm volatile("cp.async.commit_group;");
    }

    if (t < U_) sMt[t] = g_Mtop[bh * U_ + t];
    __syncthreads();

#pragma unroll
    for (int i = 0; i < 3; i++) {
        int e = t + i * 256;
        int u = e >> 4, c = e & 15;
        float4 q = make_float4(0.f, 0.f, 0.f, 0.f);
        if (u < U_)
            q = *(const float4*)(Q + ((b * L_ + sMt[u]) * H_ + h) * D_ + c * 4);
        *(float4*)(sQE + u * 64 + c * 4) = q;
    }
#pragma unroll
    for (int i = 0; i < 16; i++) {
        int e = t + i * 256;
        int k = e >> 6, d = e & 63;
        sKT[d * PADK + k] = K[((b * L_ + k0 + k) * H_ + h) * D_ + d];
    }
    __syncthreads();

    int kt = t & 15, ut = t >> 4;
    int kk = kt * 4, u0 = ut * 3;

    ull a00 = 0, a01 = 0, a10 = 0, a11 = 0, a20 = 0, a21 = 0;
    {
        const float* q0p = sQE + (u0 + 0) * 64;
        const float* q1p = sQE + (u0 + 1) * 64;
        const float* q2p = sQE + (u0 + 2) * 64;
#pragma unroll 4
        for (int d = 0; d < 64; d += 4) {
            float4 f0 = *(const float4*)(q0p + d);
            float4 f1 = *(const float4*)(q1p + d);
            float4 f2 = *(const float4*)(q2p + d);
#pragma unroll
            for (int j = 0; j < 4; j++) {
                ulonglong2 kv = *(const ulonglong2*)&sKT[(d + j) * PADK + kk];
                float w0 = (j == 0) ? f0.x : (j == 1) ? f0.y : (j == 2) ? f0.z : f0.w;
                float w1 = (j == 0) ? f1.x : (j == 1) ? f1.y : (j == 2) ? f1.z : f1.w;
                float w2 = (j == 0) ? f2.x : (j == 1) ? f2.y : (j == 2) ? f2.z : f2.w;
                ull q0, q1, q2;
                DUP2(q0, w0); DUP2(q1, w1); DUP2(q2, w2);
                FMA2(a00, q0, kv.x); FMA2(a01, q0, kv.y);
                FMA2(a10, q1, kv.x); FMA2(a11, q1, kv.y);
                FMA2(a20, q2, kv.x); FMA2(a21, q2, kv.y);
            }
        }
    }

    float ev[3][4];
    {
        const float sc = 0.125f;
        ull ra[3][2] = {{a00, a01}, {a10, a11}, {a20, a21}};
#pragma unroll
        for (int jj = 0; jj < 3; jj++) {
            float s0 = lo2(ra[jj][0]) * sc, s1 = hi2(ra[jj][0]) * sc;
            float s2 = lo2(ra[jj][1]) * sc, s3 = hi2(ra[jj][1]) * sc;
            float mm = fmaxf(fmaxf(s0, s1), fmaxf(s2, s3));
            mm = fmaxf(mm, __shfl_xor_sync(0xffffffffu, mm, 1));
            mm = fmaxf(mm, __shfl_xor_sync(0xffffffffu, mm, 2));
            mm = fmaxf(mm, __shfl_xor_sync(0xffffffffu, mm, 4));
            mm = fmaxf(mm, __shfl_xor_sync(0xffffffffu, mm, 8));
            float e0 = __expf(s0 - mm), e1 = __expf(s1 - mm);
            float e2 = __expf(s2 - mm), e3 = __expf(s3 - mm);
            float ss = (e0 + e1) + (e2 + e3);
            ss += __shfl_xor_sync(0xffffffffu, ss, 1);
            ss += __shfl_xor_sync(0xffffffffu, ss, 2);
            ss += __shfl_xor_sync(0xffffffffu, ss, 4);
            ss += __shfl_xor_sync(0xffffffffu, ss, 8);
            ev[jj][0] = e0; ev[jj][1] = e1; ev[jj][2] = e2; ev[jj][3] = e3;
            int u = u0 + jj;
            if (kt == 0 && u < U_) {
                g_pm[(bh * NSPLIT + sp) * U_ + u] = mm;
                g_ps[(bh * NSPLIT + sp) * U_ + u] = ss;
            }
        }
    }
    __syncthreads();

#pragma unroll
    for (int jj = 0; jj < 3; jj++)
        *(float4*)(sQE + (u0 + jj) * 64 + kk) =
            make_float4(ev[jj][0], ev[jj][1], ev[jj][2], ev[jj][3]);

    asm volatile("cp.async.wait_group 0;");
    __syncthreads();

    {
        int dd = kk;
        ull c00 = 0, c01 = 0, c10 = 0, c11 = 0, c20 = 0, c21 = 0;
        const float* e0p = sQE + (u0 + 0) * 64;
        const float* e1p = sQE + (u0 + 1) * 64;
        const float* e2p = sQE + (u0 + 2) * 64;
#pragma unroll 4
        for (int k = 0; k < 64; k += 4) {
            float4 f0 = *(const float4*)(e0p + k);
            float4 f1 = *(const float4*)(e1p + k);
            float4 f2 = *(const float4*)(e2p + k);
#pragma unroll
            for (int j = 0; j < 4; j++) {
                ulonglong2 vv = *(const ulonglong2*)&sV[(k + j) * PADK + dd];
                float w0 = (j == 0) ? f0.x : (j == 1) ? f0.y : (j == 2) ? f0.z : f0.w;
                float w1 = (j == 0) ? f1.x : (j == 1) ? f1.y : (j == 2) ? f1.z : f1.w;
                float w2 = (j == 0) ? f2.x : (j == 1) ? f2.y : (j == 2) ? f2.z : f2.w;
                ull e0, e1, e2;
                DUP2(e0, w0); DUP2(e1, w1); DUP2(e2, w2);
                FMA2(c00, e0, vv.x); FMA2(c01, e0, vv.y);
                FMA2(c10, e1, vv.x); FMA2(c11, e1, vv.y);
                FMA2(c20, e2, vv.x); FMA2(c21, e2, vv.y);
            }
        }
        float* pa = g_pacc + (size_t)(bh * NSPLIT + sp) * U_ * D_;
        if (u0 + 0 < U_)
            *(float4*)&pa[(u0 + 0) * D_ + dd] =
                make_float4(lo2(c00), hi2(c00), lo2(c01), hi2(c01));
        if (u0 + 1 < U_)
            *(float4*)&pa[(u0 + 1) * D_ + dd] =
                make_float4(lo2(c10), hi2(c10), lo2(c11), hi2(c11));
        if (u0 + 2 < U_)
            *(float4*)&pa[(u0 + 2) * D_ + dd] =
                make_float4(lo2(c20), hi2(c20), lo2(c21), hi2(c21));
    }
}

// ---------------------------------------------------------------------------
// Kernel 6: combine partials. grid = (U_, B*H), 64 threads.
// Also resets g_cnt for the next graph replay (u==0 block).
// ---------------------------------------------------------------------------
__global__ void __launch_bounds__(64) kernel_combine(float* __restrict__ out) {
    __shared__ float sw[NSPLIT];
    __shared__ float red[64];
    int u = blockIdx.x;
    int bh = blockIdx.y;
    int h = bh & 7, b = bh >> 3;
    int t = threadIdx.x;

    if (u == 0 && t == 0) g_cnt[bh] = 0;   // reset fused-topk counter

    float m = g_pm[(bh * NSPLIT + t) * U_ + u];
    float s = g_ps[(bh * NSPLIT + t) * U_ + u];
    red[t] = m;
    __syncthreads();
    for (int st = 32; st; st >>= 1) {
        if (t < st) red[t] = fmaxf(red[t], red[t + st]);
        __syncthreads();
    }
    float M = red[0];
    __syncthreads();
    float e = __expf(m - M);
    red[t] = e * s;
    __syncthreads();
    for (int st = 32; st; st >>= 1) {
        if (t < st) red[t] += red[t + st];
        __syncthreads();
    }
    float inv = 1.0f / red[0];
    sw[t] = e * inv;
    __syncthreads();

    float acc = 0.0f;
    const float* pa = g_pacc + (size_t)bh * NSPLIT * U_ * D_ + u * D_ + t;
#pragma unroll 8
    for (int sp = 0; sp < NSPLIT; sp++)
        acc += pa[(size_t)sp * U_ * D_] * sw[sp];
    int lsel = g_Mtop[bh * U_ + u];
    out[((b * L_ + lsel) * H_ + h) * D_ + t] = acc;
}

// ---------------------------------------------------------------------------
// Launch: main = M(+fused topk), attn, combine;
// side s2 = zero, mean, fill overlapped under M; join before combine.
// Call order keeps attn as the 4th submission (ncu capture slot).
// ---------------------------------------------------------------------------
extern "C" void kernel_launch(void* const* d_in, const int* in_sizes, int n_in,
                              void* d_out, int out_size) {
    const float* Q = (const float*)d_in[0];
    const float* K = (const float*)d_in[1];
    const float* V = (const float*)d_in[2];
    const int* idx = (const int*)d_in[3];   // int32 (JAX x64 disabled)
    float* out = (float*)d_out;

    static cudaStream_t s2 = nullptr;
    static cudaEvent_t evFork = nullptr, evJoin = nullptr;
    if (s2 == nullptr) {
        cudaStreamCreateWithFlags(&s2, cudaStreamNonBlocking);
        cudaEventCreateWithFlags(&evFork, cudaEventDisableTiming);
        cudaEventCreateWithFlags(&evJoin, cudaEventDisableTiming);
        cudaFuncSetAttribute((const void*)kernel_attn_part,
                             cudaFuncAttributeMaxDynamicSharedMemorySize, SMEM_BYTES);
    }

    // Fork side stream off the (possibly capturing) legacy stream.
    cudaEventRecord(evFork, 0);
    cudaStreamWaitEvent(s2, evFork, 0);

    // 1: M + fused topk (main)
    kernel_M<<<(B_ * H_ * L_) / 8, 256>>>(Q, K, idx);
    // 2,3: side chain on s2 (runs concurrently with kernel_M)
    kernel_zero_mean<<<(B_ * H_ * D_ + 255) / 256, 256, 0, s2>>>();
    kernel_mean_part<<<B_ * H_ * 32, 256, 0, s2>>>(V);
    // 4: attn (main; ncu capture slot)
    kernel_attn_part<<<B_ * H_ * NSPLIT, 256, SMEM_BYTES>>>(Q, K, V);
    // 5: fill (s2)
    kernel_fill<<<(B_ * L_ * H_ * D_ / 4 + 255) / 256, 256, 0, s2>>>(out);

    // Join side stream back, then combine (needs pacc + fill-complete).
    cudaEventRecord(evJoin, s2);
    cudaStreamWaitEvent(0, evJoin, 0);
    kernel_combine<<<dim3(U_, B_ * H_), 64>>>(out);
}

// round 17
// speedup vs baseline: 1.1330x; 1.1157x over previous
#include <cuda_runtime.h>
#include <math_constants.h>

// ProbAttention: B=4, L=4096, H=8, D=64, FACTOR=5
#define B_ 4
#define L_ 4096
#define H_ 8
#define D_ 64
#define SK_ 45
#define U_  45
#define NSPLIT 64
#define KC 64          // keys per split = L_/NSPLIT
#define PADK 68        // K/V tile pad (load-bearing, R15)
#define PADQ 68        // Q/E row pad (kills 2-way conflict on q/e loads)

// Scratch (device globals; no allocation allowed)
__device__ float g_M[B_ * H_ * L_];
__device__ int   g_Mtop[B_ * H_ * U_];
__device__ float g_vmean[B_ * H_ * D_];
__device__ float g_pm[B_ * H_ * NSPLIT * U_];
__device__ float g_ps[B_ * H_ * NSPLIT * U_];
__device__ float g_pacc[B_ * H_ * NSPLIT * U_ * D_];   // 23.6 MB

typedef unsigned long long ull;
__device__ __forceinline__ float lo2(ull v) { return __uint_as_float((unsigned)v); }
__device__ __forceinline__ float hi2(ull v) { return __uint_as_float((unsigned)(v >> 32)); }
#define FMA2(acc, a, b) asm("fma.rn.f32x2 %0, %1, %2, %0;" : "+l"(acc) : "l"(a), "l"(b))
#define DUP2(out, x) asm("mov.b64 %0, {%1, %1};" : "=l"(out) : "r"(__float_as_uint(x)))

__device__ __forceinline__ unsigned smem_u32(const void* p) {
    return (unsigned)__cvta_generic_to_shared(p);
}

// ---------------------------------------------------------------------------
// Kernel 1: M scores — monolithic gather kernel, AT the LTS cap (127us).
// No fragmentation (R13), no chunking (R8/R11/R12), no smem attachments (R16).
// ---------------------------------------------------------------------------
__global__ void __launch_bounds__(256) kernel_M(const float* __restrict__ Q,
                                                const float* __restrict__ K,
                                                const int* __restrict__ idx) {
    int j = (blockIdx.x * 111) & 16383;      // bijective remap
    int w = j * 8 + (threadIdx.x >> 5);
    int lane = threadIdx.x & 31;
    int li = lane & 7;
    int g  = lane >> 3;
    int l = w & (L_ - 1);
    int h = (w >> 12) & (H_ - 1);
    int b = w >> 15;

    const float4* q4 = (const float4*)(Q + ((b * L_ + l) * H_ + h) * D_);
    float4 qa = q4[li * 2];
    float4 qb = q4[li * 2 + 1];

    const int* ip = idx + l * SK_;
    float mx = -CUDART_INF_F;
    float sm = 0.0f;
#pragma unroll
    for (int sg = 0; sg < 12; sg++) {
        int s = sg * 4 + g;
        bool valid = (s < SK_);
        int kr = ip[valid ? s : 0];
        const float4* k4 = (const float4*)(K + ((b * L_ + kr) * H_ + h) * D_);
        float4 ka = k4[li * 2];
        float4 kb = k4[li * 2 + 1];
        float d = qa.x * ka.x + qa.y * ka.y + qa.z * ka.z + qa.w * ka.w
                + qb.x * kb.x + qb.y * kb.y + qb.z * kb.z + qb.w * kb.w;
        d += __shfl_xor_sync(0xffffffffu, d, 4);
        d += __shfl_xor_sync(0xffffffffu, d, 2);
        d += __shfl_xor_sync(0xffffffffu, d, 1);
        if (valid) { mx = fmaxf(mx, d); sm += d; }
    }
    mx = fmaxf(mx, __shfl_xor_sync(0xffffffffu, mx, 8));
    mx = fmaxf(mx, __shfl_xor_sync(0xffffffffu, mx, 16));
    sm += __shfl_xor_sync(0xffffffffu, sm, 8);
    sm += __shfl_xor_sync(0xffffffffu, sm, 16);
    if (lane == 0) g_M[w] = mx - sm * (1.0f / (float)L_);
}

// ---------------------------------------------------------------------------
// Kernel 2: top-U per (b,h): two-level radix histogram + exact tail select.
// 512 threads (halves every scan pass vs 256).
// ---------------------------------------------------------------------------
__device__ __forceinline__ unsigned f2key(float f) {
    unsigned u = __float_as_uint(f);
    return (u & 0x80000000u) ? ~u : (u | 0x80000000u);
}

__global__ void __launch_bounds__(512) kernel_topk() {
    __shared__ unsigned skeys[L_];
    __shared__ int hist[256];
    __shared__ unsigned candKey[1024];
    __shared__ int candIdx[1024];
    __shared__ int sT1, sN1, sT2;
    __shared__ int cSel, cCand;
    __shared__ unsigned rk[512];
    __shared__ int ri[512];

    int bh = blockIdx.x;
    int t = threadIdx.x;
    const float* m = g_M + bh * L_;
    for (int i = t; i < L_; i += 512) skeys[i] = f2key(m[i]);
    if (t < 256) hist[t] = 0;
    __syncthreads();

    for (int i = t; i < L_; i += 512) atomicAdd(&hist[skeys[i] >> 24], 1);
    __syncthreads();
    if (t == 0) {
        int acc = 0;
        for (int bin = 255; bin >= 0; bin--) {
            if (acc + hist[bin] >= U_) { sT1 = bin; sN1 = acc; break; }
            acc += hist[bin];
        }
    }
    __syncthreads();
    int T1 = sT1, n1 = sN1;
    if (t < 256) hist[t] = 0;
    __syncthreads();

    for (int i = t; i < L_; i += 512)
        if ((int)(skeys[i] >> 24) == T1) atomicAdd(&hist[(skeys[i] >> 16) & 255], 1);
    __syncthreads();
    if (t == 0) {
        int acc = n1;
        for (int bin = 255; bin >= 0; bin--) {
            if (acc + hist[bin] >= U_) { sT2 = bin; break; }
            acc += hist[bin];
        }
        cSel = 0; cCand = 0;
    }
    __syncthreads();
    unsigned TH16 = ((unsigned)T1 << 8) | (unsigned)sT2;

    for (int i = t; i < L_; i += 512) {
        unsigned k16 = skeys[i] >> 16;
        if (k16 > TH16) {
            int pos = atomicAdd(&cSel, 1);
            g_Mtop[bh * U_ + pos] = i;
        } else if (k16 == TH16) {
            int pos = atomicAdd(&cCand, 1);
            if (pos < 1024) { candKey[pos] = skeys[i]; candIdx[pos] = i; }
        }
    }
    __syncthreads();
    int ndef = cSel;
    int need = U_ - ndef;
    int nc = (cCand < 1024) ? cCand : 1024;

    for (int it = 0; it < need; it++) {
        unsigned best = 0; int bi = -1;
        for (int jj = t; jj < nc; jj += 512) {
            unsigned v = candKey[jj];
            if (v > best) { best = v; bi = jj; }
        }
        rk[t] = best; ri[t] = bi;
        __syncthreads();
        for (int s = 256; s; s >>= 1) {
            if (t < s && rk[t + s] > rk[t]) { rk[t] = rk[t + s]; ri[t] = ri[t + s]; }
            __syncthreads();
        }
        if (t == 0) {
            g_Mtop[bh * U_ + ndef + it] = candIdx[ri[0]];
            candKey[ri[0]] = 0;
        }
        __syncthreads();
    }
}

// ---------------------------------------------------------------------------
// Kernel 3: V mean (zero + float4 partial sums)
// ---------------------------------------------------------------------------
__global__ void kernel_zero_mean() {
    int i = blockIdx.x * blockDim.x + threadIdx.x;
    if (i < B_ * H_ * D_) g_vmean[i] = 0.0f;
}

__global__ void __launch_bounds__(256) kernel_mean_part(const float* __restrict__ V) {
    int blk = blockIdx.x;              // 1024 blocks
    int seg = blk & 31;
    int bh = blk >> 5;
    int h = bh & (H_ - 1);
    int b = bh >> 3;
    int t = threadIdx.x;
    int d4 = t & 15;
    int sub = t >> 4;
    int l0 = seg * 128;
    const float4* V4 = (const float4*)V;
    float ax = 0.f, ay = 0.f, az = 0.f, aw = 0.f;
#pragma unroll
    for (int i = 0; i < 8; i++) {
        int l = l0 + sub + i * 16;
        float4 v = V4[((size_t)(b * L_ + l) * H_ + h) * 16 + d4];
        ax += v.x; ay += v.y; az += v.z; aw += v.w;
    }
    __shared__ float4 s[16][16];
    s[sub][d4] = make_float4(ax, ay, az, aw);
    __syncthreads();
    if (t < 16) {
        float tx = 0.f, ty = 0.f, tz = 0.f, tw = 0.f;
#pragma unroll
        for (int jj = 0; jj < 16; jj++) {
            float4 v = s[jj][t];
            tx += v.x; ty += v.y; tz += v.z; tw += v.w;
        }
        atomicAdd(&g_vmean[bh * D_ + t * 4 + 0], tx);
        atomicAdd(&g_vmean[bh * D_ + t * 4 + 1], ty);
        atomicAdd(&g_vmean[bh * D_ + t * 4 + 2], tz);
        atomicAdd(&g_vmean[bh * D_ + t * 4 + 3], tw);
    }
}

// ---------------------------------------------------------------------------
// Kernel 4: fill out with V-mean broadcast (float4 stores)
// ---------------------------------------------------------------------------
__global__ void kernel_fill(float* __restrict__ out) {
    unsigned i = blockIdx.x * blockDim.x + threadIdx.x;  // float4 index
    int d4 = i & 15;
    int h = (i >> 4) & 7;
    int b = i >> 19;
    const float4* vm4 = (const float4*)g_vmean;
    float4 v = vm4[(b * H_ + h) * 16 + d4];
    const float inv = 1.0f / (float)L_;
    ((float4*)out)[i] = make_float4(v.x * inv, v.y * inv, v.z * inv, v.w * inv);
}

// ---------------------------------------------------------------------------
// Kernel 5: split-KV attention — R14 version + PADQ=68 on the Q/E buffer
// (q/e rows 3 apart were 768B ≡ 0 mod 128 -> 2-way conflict every load;
// stride 68 staggers them).
// ---------------------------------------------------------------------------
#define OFF_V   (64 * PADK)
#define OFF_QE  (OFF_V + 64 * PADK)
#define OFF_MT  (OFF_QE + 48 * PADQ)
#define SMEM_FLOATS (OFF_MT + 64)
#define SMEM_BYTES  (SMEM_FLOATS * 4)

__global__ void __launch_bounds__(256) kernel_attn_part(
        const float* __restrict__ Q,
        const float* __restrict__ K,
        const float* __restrict__ V) {
    extern __shared__ float smem[];
    float* sKT = smem;                  // [64][PADK]  K transposed [d][k]
    float* sV  = smem + OFF_V;          // [64][PADK]  V natural   [k][d]
    float* sQE = smem + OFF_QE;         // [48][PADQ]  Q rows, then E rows
    int*   sMt = (int*)(smem + OFF_MT);

    int bh = blockIdx.x >> 6;
    int sp = blockIdx.x & 63;
    int h = bh & 7, b = bh >> 3;
    int k0 = sp * KC;
    int t = threadIdx.x;

    {
        const char* vbase = (const char*)(V + ((size_t)(b * L_ + k0) * H_ + h) * D_);
#pragma unroll
        for (int i = 0; i < 4; i++) {
            int e = t + i * 256;
            int row = e >> 4, c = e & 15;
            unsigned dst = smem_u32(sV + row * PADK + c * 4);
            const char* src = vbase + (size_t)row * (H_ * D_ * 4) + c * 16;
            asm volatile("cp.async.cg.shared.global [%0], [%1], 16;"
                         :: "r"(dst), "l"(src));
        }
        asm volatile("cp.async.commit_group;");
    }

    if (t < U_) sMt[t] = g_Mtop[bh * U_ + t];
    __syncthreads();

#pragma unroll
    for (int i = 0; i < 3; i++) {
        int e = t + i * 256;
        int u = e >> 4, c = e & 15;
        float4 q = make_float4(0.f, 0.f, 0.f, 0.f);
        if (u < U_)
            q = *(const float4*)(Q + ((b * L_ + sMt[u]) * H_ + h) * D_ + c * 4);
        *(float4*)(sQE + u * PADQ + c * 4) = q;
    }
#pragma unroll
    for (int i = 0; i < 16; i++) {
        int e = t + i * 256;
        int k = e >> 6, d = e & 63;
        sKT[d * PADK + k] = K[((b * L_ + k0 + k) * H_ + h) * D_ + d];
    }
    __syncthreads();

    int kt = t & 15, ut = t >> 4;
    int kk = kt * 4, u0 = ut * 3;

    ull a00 = 0, a01 = 0, a10 = 0, a11 = 0, a20 = 0, a21 = 0;
    {
        const float* q0p = sQE + (u0 + 0) * PADQ;
        const float* q1p = sQE + (u0 + 1) * PADQ;
        const float* q2p = sQE + (u0 + 2) * PADQ;
#pragma unroll 4
        for (int d = 0; d < 64; d += 4) {
            float4 f0 = *(const float4*)(q0p + d);
            float4 f1 = *(const float4*)(q1p + d);
            float4 f2 = *(const float4*)(q2p + d);
#pragma unroll
            for (int j = 0; j < 4; j++) {
                ulonglong2 kv = *(const ulonglong2*)&sKT[(d + j) * PADK + kk];
                float w0 = (j == 0) ? f0.x : (j == 1) ? f0.y : (j == 2) ? f0.z : f0.w;
                float w1 = (j == 0) ? f1.x : (j == 1) ? f1.y : (j == 2) ? f1.z : f1.w;
                float w2 = (j == 0) ? f2.x : (j == 1) ? f2.y : (j == 2) ? f2.z : f2.w;
                ull q0, q1, q2;
                DUP2(q0, w0); DUP2(q1, w1); DUP2(q2, w2);
                FMA2(a00, q0, kv.x); FMA2(a01, q0, kv.y);
                FMA2(a10, q1, kv.x); FMA2(a11, q1, kv.y);
                FMA2(a20, q2, kv.x); FMA2(a21, q2, kv.y);
            }
        }
    }

    float ev[3][4];
    {
        const float sc = 0.125f;
        ull ra[3][2] = {{a00, a01}, {a10, a11}, {a20, a21}};
#pragma unroll
        for (int jj = 0; jj < 3; jj++) {
            float s0 = lo2(ra[jj][0]) * sc, s1 = hi2(ra[jj][0]) * sc;
            float s2 = lo2(ra[jj][1]) * sc, s3 = hi2(ra[jj][1]) * sc;
            float mm = fmaxf(fmaxf(s0, s1), fmaxf(s2, s3));
            mm = fmaxf(mm, __shfl_xor_sync(0xffffffffu, mm, 1));
            mm = fmaxf(mm, __shfl_xor_sync(0xffffffffu, mm, 2));
            mm = fmaxf(mm, __shfl_xor_sync(0xffffffffu, mm, 4));
            mm = fmaxf(mm, __shfl_xor_sync(0xffffffffu, mm, 8));
            float e0 = __expf(s0 - mm), e1 = __expf(s1 - mm);
            float e2 = __expf(s2 - mm), e3 = __expf(s3 - mm);
            float ss = (e0 + e1) + (e2 + e3);
            ss += __shfl_xor_sync(0xffffffffu, ss, 1);
            ss += __shfl_xor_sync(0xffffffffu, ss, 2);
            ss += __shfl_xor_sync(0xffffffffu, ss, 4);
            ss += __shfl_xor_sync(0xffffffffu, ss, 8);
            ev[jj][0] = e0; ev[jj][1] = e1; ev[jj][2] = e2; ev[jj][3] = e3;
            int u = u0 + jj;
            if (kt == 0 && u < U_) {
                g_pm[(bh * NSPLIT + sp) * U_ + u] = mm;
                g_ps[(bh * NSPLIT + sp) * U_ + u] = ss;
            }
        }
    }
    __syncthreads();

#pragma unroll
    for (int jj = 0; jj < 3; jj++)
        *(float4*)(sQE + (u0 + jj) * PADQ + kk) =
            make_float4(ev[jj][0], ev[jj][1], ev[jj][2], ev[jj][3]);

    asm volatile("cp.async.wait_group 0;");
    __syncthreads();

    {
        int dd = kk;
        ull c00 = 0, c01 = 0, c10 = 0, c11 = 0, c20 = 0, c21 = 0;
        const float* e0p = sQE + (u0 + 0) * PADQ;
        const float* e1p = sQE + (u0 + 1) * PADQ;
        const float* e2p = sQE + (u0 + 2) * PADQ;
#pragma unroll 4
        for (int k = 0; k < 64; k += 4) {
            float4 f0 = *(const float4*)(e0p + k);
            float4 f1 = *(const float4*)(e1p + k);
            float4 f2 = *(const float4*)(e2p + k);
#pragma unroll
            for (int j = 0; j < 4; j++) {
                ulonglong2 vv = *(const ulonglong2*)&sV[(k + j) * PADK + dd];
                float w0 = (j == 0) ? f0.x : (j == 1) ? f0.y : (j == 2) ? f0.z : f0.w;
                float w1 = (j == 0) ? f1.x : (j == 1) ? f1.y : (j == 2) ? f1.z : f1.w;
                float w2 = (j == 0) ? f2.x : (j == 1) ? f2.y : (j == 2) ? f2.z : f2.w;
                ull e0, e1, e2;
                DUP2(e0, w0); DUP2(e1, w1); DUP2(e2, w2);
                FMA2(c00, e0, vv.x); FMA2(c01, e0, vv.y);
                FMA2(c10, e1, vv.x); FMA2(c11, e1, vv.y);
                FMA2(c20, e2, vv.x); FMA2(c21, e2, vv.y);
            }
        }
        float* pa = g_pacc + (size_t)(bh * NSPLIT + sp) * U_ * D_;
        if (u0 + 0 < U_)
            *(float4*)&pa[(u0 + 0) * D_ + dd] =
                make_float4(lo2(c00), hi2(c00), lo2(c01), hi2(c01));
        if (u0 + 1 < U_)
            *(float4*)&pa[(u0 + 1) * D_ + dd] =
                make_float4(lo2(c10), hi2(c10), lo2(c11), hi2(c11));
        if (u0 + 2 < U_)
            *(float4*)&pa[(u0 + 2) * D_ + dd] =
                make_float4(lo2(c20), hi2(c20), lo2(c21), hi2(c21));
    }
}

// ---------------------------------------------------------------------------
// Kernel 6: combine partials. grid = (U_, B*H), 64 threads.
// ---------------------------------------------------------------------------
__global__ void __launch_bounds__(64) kernel_combine(float* __restrict__ out) {
    __shared__ float sw[NSPLIT];
    __shared__ float red[64];
    int u = blockIdx.x;
    int bh = blockIdx.y;
    int h = bh & 7, b = bh >> 3;
    int t = threadIdx.x;

    float m = g_pm[(bh * NSPLIT + t) * U_ + u];
    float s = g_ps[(bh * NSPLIT + t) * U_ + u];
    red[t] = m;
    __syncthreads();
    for (int st = 32; st; st >>= 1) {
        if (t < st) red[t] = fmaxf(red[t], red[t + st]);
        __syncthreads();
    }
    float M = red[0];
    __syncthreads();
    float e = __expf(m - M);
    red[t] = e * s;
    __syncthreads();
    for (int st = 32; st; st >>= 1) {
        if (t < st) red[t] += red[t + st];
        __syncthreads();
    }
    float inv = 1.0f / red[0];
    sw[t] = e * inv;
    __syncthreads();

    float acc = 0.0f;
    const float* pa = g_pacc + (size_t)bh * NSPLIT * U_ * D_ + u * D_ + t;
#pragma unroll 8
    for (int sp = 0; sp < NSPLIT; sp++)
        acc += pa[(size_t)sp * U_ * D_] * sw[sp];
    int lsel = g_Mtop[bh * U_ + u];
    out[((b * L_ + lsel) * H_ + h) * D_ + t] = acc;
}

// ---------------------------------------------------------------------------
// Launch (R10/R14 structure): main = M, topk, attn, combine;
// side s2 = zero, mean, fill overlapped under M; join before combine.
// ---------------------------------------------------------------------------
extern "C" void kernel_launch(void* const* d_in, const int* in_sizes, int n_in,
                              void* d_out, int out_size) {
    const float* Q = (const float*)d_in[0];
    const float* K = (const float*)d_in[1];
    const float* V = (const float*)d_in[2];
    const int* idx = (const int*)d_in[3];   // int32 (JAX x64 disabled)
    float* out = (float*)d_out;

    static cudaStream_t s2 = nullptr;
    static cudaEvent_t evFork = nullptr, evJoin = nullptr;
    if (s2 == nullptr) {
        cudaStreamCreateWithFlags(&s2, cudaStreamNonBlocking);
        cudaEventCreateWithFlags(&evFork, cudaEventDisableTiming);
        cudaEventCreateWithFlags(&evJoin, cudaEventDisableTiming);
        cudaFuncSetAttribute((const void*)kernel_M,
                             cudaFuncAttributePreferredSharedMemoryCarveout, 0);
        cudaFuncSetAttribute((const void*)kernel_attn_part,
                             cudaFuncAttributeMaxDynamicSharedMemorySize, SMEM_BYTES);
    }

    // Fork side stream off the (possibly capturing) legacy stream.
    cudaEventRecord(evFork, 0);
    cudaStreamWaitEvent(s2, evFork, 0);

    // Main chain (submissions 1,2; slot-4 ncu capture lands on attn below)
    kernel_M<<<(B_ * H_ * L_) / 8, 256>>>(Q, K, idx);
    kernel_topk<<<B_ * H_, 512>>>();

    // Side chain on s2 (runs concurrently with kernel_M)
    kernel_zero_mean<<<(B_ * H_ * D_ + 255) / 256, 256, 0, s2>>>();

    // submission 4: attn (main chain)
    kernel_attn_part<<<B_ * H_ * NSPLIT, 256, SMEM_BYTES>>>(Q, K, V);

    kernel_mean_part<<<B_ * H_ * 32, 256, 0, s2>>>(V);
    kernel_fill<<<(B_ * L_ * H_ * D_ / 4 + 255) / 256, 256, 0, s2>>>(out);

    // Join side stream back, then combine (needs pacc + fill-complete).
    cudaEventRecord(evJoin, s2);
    cudaStreamWaitEvent(0, evJoin, 0);
    kernel_combine<<<dim3(U_, B_ * H_), 64>>>(out);
}